// round 2
// baseline (speedup 1.0000x reference)
#include <cuda_runtime.h>
#include <cuda_bf16.h>
#include <stdint.h>

#define TS   512
#define BA   64
#define DI   512
#define HID  512
#define NG   2048          // 4 gates * HID; gate order 0=i,1=f,2=o,3=c
#define TBM  (TS*BA)
#define GBLK 128           // persistent blocks (co-resident on 148 SMs)

// ----------------- device-global scratch (no cudaMalloc allowed) -----------------
static __device__ __align__(16) __nv_bfloat16 g_Ahi[(size_t)TBM*DI];
static __device__ __align__(16) __nv_bfloat16 g_Alo[(size_t)TBM*DI];
static __device__ __align__(16) __nv_bfloat16 g_WxThi[(size_t)NG*DI];   // [c][d], K-major
static __device__ __align__(16) __nv_bfloat16 g_WxTlo[(size_t)NG*DI];
static __device__ __align__(16) __nv_bfloat16 g_WhThi[(size_t)NG*HID];  // [c][k], K-major
static __device__ __align__(16) __nv_bfloat16 g_WhTlo[(size_t)NG*HID];
static __device__ __align__(16) float         g_bias[NG];
static __device__ __align__(16) float         g_X[(size_t)TBM*NG];      // x-projections (+bias)
static __device__ __align__(16) __nv_bfloat16 g_HFhi[2][BA*HID];        // H, fragment-interleaved
static __device__ __align__(16) __nv_bfloat16 g_HFlo[2][BA*HID];
static __device__ volatile int g_cnt;
static __device__ volatile int g_phase;

// ----------------- helpers -----------------
__device__ __forceinline__ void split_bf16(float v, __nv_bfloat16& hi, __nv_bfloat16& lo) {
    hi = __float2bfloat16(v);
    lo = __float2bfloat16(v - __bfloat162float(hi));
}

__device__ __forceinline__ void mma16816(float* c,
                                         uint32_t a0, uint32_t a1, uint32_t a2, uint32_t a3,
                                         uint32_t b0, uint32_t b1) {
    asm volatile(
        "mma.sync.aligned.m16n8k16.row.col.f32.bf16.bf16.f32 "
        "{%0,%1,%2,%3},{%4,%5,%6,%7},{%8,%9},{%0,%1,%2,%3};\n"
        : "+f"(c[0]), "+f"(c[1]), "+f"(c[2]), "+f"(c[3])
        : "r"(a0), "r"(a1), "r"(a2), "r"(a3), "r"(b0), "r"(b1));
}

__device__ __forceinline__ float sigf(float x) { return 1.f / (1.f + __expf(-x)); }
__device__ __forceinline__ float tanhfast(float x) {
    float ax = fminf(fmaxf(x, -15.f), 15.f);
    float e  = __expf(2.f * ax);
    return (e - 1.f) / (e + 1.f);
}

__device__ __forceinline__ int cglob_f(int cl, int blk) {
    return (cl >> 2) * HID + blk * 4 + (cl & 3);
}

__device__ __forceinline__ void st_cg_b16(__nv_bfloat16* p, __nv_bfloat16 v) {
    unsigned short u = *(unsigned short*)&v;
    asm volatile("st.global.cg.b16 [%0], %1;" :: "l"(p), "h"(u) : "memory");
}

// ----------------- init: zero H buffers + barrier state -----------------
__global__ void k_init() {
    int i = blockIdx.x * blockDim.x + threadIdx.x;
    if (i < 2 * BA * HID) {
        ((__nv_bfloat16*)g_HFhi)[i] = __float2bfloat16(0.f);
        ((__nv_bfloat16*)g_HFlo)[i] = __float2bfloat16(0.f);
    }
    if (i == 0) { g_cnt = 0; g_phase = 0; }
}

// ----------------- inputs -> split bf16 -----------------
__global__ void k_conv_in(const float* __restrict__ in) {
    size_t i = (size_t)blockIdx.x * blockDim.x + threadIdx.x;
    const size_t n4 = (size_t)TBM * DI / 4;
    if (i >= n4) return;
    float4 v = reinterpret_cast<const float4*>(in)[i];
    __nv_bfloat16 h0,h1,h2,h3,l0,l1,l2,l3;
    split_bf16(v.x, h0, l0); split_bf16(v.y, h1, l1);
    split_bf16(v.z, h2, l2); split_bf16(v.w, h3, l3);
    __nv_bfloat162* ph = reinterpret_cast<__nv_bfloat162*>(g_Ahi + 4*i);
    __nv_bfloat162* pl = reinterpret_cast<__nv_bfloat162*>(g_Alo + 4*i);
    ph[0] = __halves2bfloat162(h0, h1); ph[1] = __halves2bfloat162(h2, h3);
    pl[0] = __halves2bfloat162(l0, l1); pl[1] = __halves2bfloat162(l2, l3);
}

// ----------------- weights -> split bf16, transposed K-major; combine biases -----------------
__global__ void k_conv_w(const float* __restrict__ Wxi, const float* __restrict__ Wxf,
                         const float* __restrict__ Wxo, const float* __restrict__ Wxc,
                         const float* __restrict__ Whi, const float* __restrict__ Whf,
                         const float* __restrict__ Who, const float* __restrict__ Whc,
                         const float* __restrict__ bi,  const float* __restrict__ bff,
                         const float* __restrict__ bo,  const float* __restrict__ bc) {
    const int NW = NG * DI;
    int stride = gridDim.x * blockDim.x;
    for (int i = blockIdx.x * blockDim.x + threadIdx.x; i < 2*NW + NG; i += stride) {
        if (i < NW) {                       // WxT[c][d] = Wx_g[d][h]
            int c = i >> 9, d = i & 511;
            int gg = c >> 9, h = c & 511;
            const float* W = gg == 0 ? Wxi : (gg == 1 ? Wxf : (gg == 2 ? Wxo : Wxc));
            __nv_bfloat16 hi, lo; split_bf16(W[d*HID + h], hi, lo);
            g_WxThi[i] = hi; g_WxTlo[i] = lo;
        } else if (i < 2*NW) {              // WhT[c][k] = Wh_g[k][h]
            int j = i - NW;
            int c = j >> 9, k = j & 511;
            int gg = c >> 9, h = c & 511;
            const float* W = gg == 0 ? Whi : (gg == 1 ? Whf : (gg == 2 ? Who : Whc));
            __nv_bfloat16 hi, lo; split_bf16(W[k*HID + h], hi, lo);
            g_WhThi[j] = hi; g_WhTlo[j] = lo;
        } else {                            // bias
            int c = i - 2*NW;
            int gg = c >> 9, h = c & 511;
            const float* bb = gg == 0 ? bi : (gg == 1 ? bff : (gg == 2 ? bo : bc));
            g_bias[c] = bb[h];
        }
    }
}

// ----------------- phase 1: g_X = inputs @ Wx + bias (split bf16, 3-term) -----------------
__global__ __launch_bounds__(256, 1) void k_gemm_x() {
    __shared__ __nv_bfloat16 Ah_s[128*40];
    __shared__ __nv_bfloat16 Al_s[128*40];
    __shared__ __nv_bfloat16 Bh_s[128*40];
    __shared__ __nv_bfloat16 Bl_s[128*40];

    const int tid = threadIdx.x, w = tid >> 5, l = tid & 31;
    const int wm = w & 3, wn = w >> 2, r = l >> 2, q = l & 3;
    const int row0 = blockIdx.x * 128, col0 = blockIdx.y * 128;

    float acc[2][8][4];
    #pragma unroll
    for (int a = 0; a < 2; a++)
        #pragma unroll
        for (int b = 0; b < 8; b++)
            #pragma unroll
            for (int c = 0; c < 4; c++) acc[a][b][c] = 0.f;

    const int lr = tid >> 1, lh = tid & 1;

    for (int ck = 0; ck < 16; ck++) {
        __syncthreads();
        {
            size_t goffA = (size_t)(row0 + lr) * DI + ck*32 + lh*16;
            size_t goffB = (size_t)(col0 + lr) * DI + ck*32 + lh*16;
            uint4 a0 = *(const uint4*)(g_Ahi + goffA);
            uint4 a1 = *(const uint4*)(g_Ahi + goffA + 8);
            uint4 a2 = *(const uint4*)(g_Alo + goffA);
            uint4 a3 = *(const uint4*)(g_Alo + goffA + 8);
            uint4 b0 = *(const uint4*)(g_WxThi + goffB);
            uint4 b1 = *(const uint4*)(g_WxThi + goffB + 8);
            uint4 b2 = *(const uint4*)(g_WxTlo + goffB);
            uint4 b3 = *(const uint4*)(g_WxTlo + goffB + 8);
            int so = lr*40 + lh*16;
            *(uint4*)&Ah_s[so]     = a0; *(uint4*)&Ah_s[so + 8] = a1;
            *(uint4*)&Al_s[so]     = a2; *(uint4*)&Al_s[so + 8] = a3;
            *(uint4*)&Bh_s[so]     = b0; *(uint4*)&Bh_s[so + 8] = b1;
            *(uint4*)&Bl_s[so]     = b2; *(uint4*)&Bl_s[so + 8] = b3;
        }
        __syncthreads();

        #pragma unroll
        for (int kt = 0; kt < 2; kt++) {
            const int ca = kt*16 + 2*q;
            uint32_t Ahf[2][4], Alf[2][4];
            #pragma unroll
            for (int mt = 0; mt < 2; mt++) {
                int ra = (wm*32 + mt*16 + r) * 40;
                Ahf[mt][0] = *(const uint32_t*)&Ah_s[ra + ca];
                Ahf[mt][1] = *(const uint32_t*)&Ah_s[ra + 320 + ca];
                Ahf[mt][2] = *(const uint32_t*)&Ah_s[ra + ca + 8];
                Ahf[mt][3] = *(const uint32_t*)&Ah_s[ra + 320 + ca + 8];
                Alf[mt][0] = *(const uint32_t*)&Al_s[ra + ca];
                Alf[mt][1] = *(const uint32_t*)&Al_s[ra + 320 + ca];
                Alf[mt][2] = *(const uint32_t*)&Al_s[ra + ca + 8];
                Alf[mt][3] = *(const uint32_t*)&Al_s[ra + 320 + ca + 8];
            }
            #pragma unroll
            for (int nt = 0; nt < 8; nt++) {
                int rb2 = (wn*64 + nt*8 + r) * 40;
                uint32_t bh0 = *(const uint32_t*)&Bh_s[rb2 + ca];
                uint32_t bh1 = *(const uint32_t*)&Bh_s[rb2 + ca + 8];
                uint32_t bl0 = *(const uint32_t*)&Bl_s[rb2 + ca];
                uint32_t bl1 = *(const uint32_t*)&Bl_s[rb2 + ca + 8];
                #pragma unroll
                for (int mt = 0; mt < 2; mt++) {
                    mma16816(acc[mt][nt], Ahf[mt][0], Ahf[mt][1], Ahf[mt][2], Ahf[mt][3], bh0, bh1);
                    mma16816(acc[mt][nt], Alf[mt][0], Alf[mt][1], Alf[mt][2], Alf[mt][3], bh0, bh1);
                    mma16816(acc[mt][nt], Ahf[mt][0], Ahf[mt][1], Ahf[mt][2], Ahf[mt][3], bl0, bl1);
                }
            }
        }
    }

    // epilogue: X = acc + bias
    #pragma unroll
    for (int mt = 0; mt < 2; mt++) {
        #pragma unroll
        for (int nt = 0; nt < 8; nt++) {
            int grow = row0 + wm*32 + mt*16 + r;
            int gcol = col0 + wn*64 + nt*8 + 2*q;
            float2 bb = *(const float2*)&g_bias[gcol];
            float2 v0 = make_float2(acc[mt][nt][0] + bb.x, acc[mt][nt][1] + bb.y);
            float2 v1 = make_float2(acc[mt][nt][2] + bb.x, acc[mt][nt][3] + bb.y);
            *(float2*)&g_X[(size_t)grow * NG + gcol]       = v0;
            *(float2*)&g_X[(size_t)(grow + 8) * NG + gcol] = v1;
        }
    }
}

// ----------------- grid barrier (sense reversal) -----------------
__device__ __forceinline__ void gridbar(int& ph) {
    __syncthreads();
    if (threadIdx.x == 0) {
        __threadfence();
        if (atomicAdd((int*)&g_cnt, 1) == GBLK - 1) {
            g_cnt = 0;
            __threadfence();
            g_phase = ph ^ 1;
        } else {
            while (g_phase == ph) { }
        }
    }
    __syncthreads();
    ph ^= 1;
}

// ----------------- phase 2: persistent LSTM recurrence -----------------
__global__ __launch_bounds__(256, 1) void k_lstm(float* __restrict__ out) {
    __shared__ __nv_bfloat16 WFlo[16*520];   // Wh-lo fragments, padded rows
    __shared__ float preA[64*20];
    __shared__ float preB[64*20];

    const int tid = threadIdx.x, w = tid >> 5, l = tid & 31;
    const int m = w & 3, kh = w >> 2, r = l >> 2, q = l & 3;
    const int blk = blockIdx.x;

    // preload Wh-hi fragments into registers (loop-invariant, half of K per warp)
    uint32_t Bh[2][16][2];
    #pragma unroll
    for (int nt = 0; nt < 2; nt++) {
        int cg = cglob_f(nt*8 + r, blk);
        const __nv_bfloat16* wp = g_WhThi + (size_t)cg * HID;
        #pragma unroll
        for (int ktl = 0; ktl < 16; ktl++) {
            int kg16 = (kh*16 + ktl) * 16;
            Bh[nt][ktl][0] = *(const uint32_t*)(wp + kg16 + 2*q);
            Bh[nt][ktl][1] = *(const uint32_t*)(wp + kg16 + 2*q + 8);
        }
    }
    // fill Wh-lo fragment smem: row n (len 520), elem (kt*4+q)*4 + j*2
    for (int i = tid; i < 4096; i += 256) {
        int j = i & 1, qq = (i >> 1) & 3, kt = (i >> 3) & 31, n = (i >> 8) & 15;
        int cg = cglob_f(n, blk);
        uint32_t v = *(const uint32_t*)(g_WhTlo + (size_t)cg * HID + kt*16 + 2*qq + 8*j);
        *(uint32_t*)&WFlo[n*520 + (kt*4 + qq)*4 + j*2] = v;
    }
    __syncthreads();

    float C = 0.f;
    int phase = 0;
    const int eb = tid >> 2, ehl = tid & 3;
    const int hg = blk*4 + ehl;
    const int wkt = hg >> 4, wkk = hg & 15;
    const int widx = ((eb*32 + wkt)*4 + ((wkk >> 1) & 3))*4 + (wkk >> 3)*2 + (wkk & 1);

    for (int t = 0; t < TS; t++) {
        const int rb = t & 1, wbuf = rb ^ 1;
        float acc[2][4];
        if (kh == 0) {   // init accumulators from precomputed X (includes bias)
            #pragma unroll
            for (int nt = 0; nt < 2; nt++) {
                int cg = cglob_f(nt*8 + 2*q, blk);
                size_t row = (size_t)(t*BA + m*16 + r);
                float2 v01 = *(const float2*)&g_X[row * NG + cg];
                float2 v23 = *(const float2*)&g_X[(row + 8) * NG + cg];
                acc[nt][0] = v01.x; acc[nt][1] = v01.y;
                acc[nt][2] = v23.x; acc[nt][3] = v23.y;
            }
        } else {
            #pragma unroll
            for (int nt = 0; nt < 2; nt++)
                #pragma unroll
                for (int c = 0; c < 4; c++) acc[nt][c] = 0.f;
        }

        gridbar(phase);   // H(t-1) writes now visible

        const __nv_bfloat16* Hh = g_HFhi[rb];
        const __nv_bfloat16* Hl = g_HFlo[rb];
        const int rA = m*16 + r;
        #pragma unroll
        for (int ktl = 0; ktl < 16; ktl++) {
            int ktg = kh*16 + ktl;
            int i0 = ((rA*32 + ktg)*4 + q)*4;
            int i1 = (((rA + 8)*32 + ktg)*4 + q)*4;
            uint2 ah0 = __ldcg((const uint2*)(Hh + i0));
            uint2 ah1 = __ldcg((const uint2*)(Hh + i1));
            uint2 al0 = __ldcg((const uint2*)(Hl + i0));
            uint2 al1 = __ldcg((const uint2*)(Hl + i1));
            #pragma unroll
            for (int nt = 0; nt < 2; nt++) {
                uint2 bl = *(const uint2*)&WFlo[(nt*8 + r)*520 + (ktg*4 + q)*4];
                mma16816(acc[nt], ah0.x, ah1.x, ah0.y, ah1.y, Bh[nt][ktl][0], Bh[nt][ktl][1]);
                mma16816(acc[nt], al0.x, al1.x, al0.y, al1.y, Bh[nt][ktl][0], Bh[nt][ktl][1]);
                mma16816(acc[nt], ah0.x, ah1.x, ah0.y, ah1.y, bl.x, bl.y);
            }
        }

        // exchange partials via smem (k-halves in separate buffers)
        float* pre = (kh == 0) ? preA : preB;
        #pragma unroll
        for (int nt = 0; nt < 2; nt++) {
            int c0 = nt*8 + 2*q;
            pre[(m*16 + r)*20 + c0]       = acc[nt][0];
            pre[(m*16 + r)*20 + c0 + 1]   = acc[nt][1];
            pre[(m*16 + r + 8)*20 + c0]     = acc[nt][2];
            pre[(m*16 + r + 8)*20 + c0 + 1] = acc[nt][3];
        }
        __syncthreads();

        float xi = preA[eb*20 + ehl]      + preB[eb*20 + ehl];
        float xf = preA[eb*20 + 4 + ehl]  + preB[eb*20 + 4 + ehl];
        float xo = preA[eb*20 + 8 + ehl]  + preB[eb*20 + 8 + ehl];
        float xc = preA[eb*20 + 12 + ehl] + preB[eb*20 + 12 + ehl];
        float I  = sigf(xi), F = sigf(xf), O = sigf(xo);
        float Ct = tanhfast(xc);
        C = F*C + I*Ct;
        float Hn = O * tanhfast(C);

        out[((size_t)t*BA + eb)*HID + hg] = Hn;
        if (t == TS - 1) {
            out[(size_t)TS*BA*HID + (size_t)eb*HID + hg]             = Hn;
            out[(size_t)TS*BA*HID + (size_t)BA*HID + (size_t)eb*HID + hg] = C;
        }
        __nv_bfloat16 hh, hl2;
        split_bf16(Hn, hh, hl2);
        st_cg_b16(&g_HFhi[wbuf][widx], hh);
        st_cg_b16(&g_HFlo[wbuf][widx], hl2);
        // visibility guaranteed by threadfence inside gridbar at next iteration
    }
}

// ----------------- launch -----------------
extern "C" void kernel_launch(void* const* d_in, const int* in_sizes, int n_in,
                              void* d_out, int out_size) {
    const float* inp = (const float*)d_in[0];
    const float* Wxi = (const float*)d_in[1];
    const float* Whi = (const float*)d_in[2];
    const float* bi  = (const float*)d_in[3];
    const float* Wxf = (const float*)d_in[4];
    const float* Whf = (const float*)d_in[5];
    const float* bf  = (const float*)d_in[6];
    const float* Wxo = (const float*)d_in[7];
    const float* Who = (const float*)d_in[8];
    const float* bo  = (const float*)d_in[9];
    const float* Wxc = (const float*)d_in[10];
    const float* Whc = (const float*)d_in[11];
    const float* bc  = (const float*)d_in[12];
    float* out = (float*)d_out;

    k_init<<<256, 256>>>();
    k_conv_in<<<16384, 256>>>(inp);
    k_conv_w<<<2048, 256>>>(Wxi, Wxf, Wxo, Wxc, Whi, Whf, Who, Whc, bi, bf, bo, bc);
    k_gemm_x<<<dim3(256, 16), 256>>>();
    k_lstm<<<GBLK, 256>>>(out);
}

// round 3
// speedup vs baseline: 1.4959x; 1.4959x over previous
#include <cuda_runtime.h>
#include <cuda_bf16.h>
#include <stdint.h>

#define TS   512
#define BA   64
#define DI   512
#define HID  512
#define NG   2048          // 4 gates * HID; gate order 0=i,1=f,2=o,3=c
#define TBM  (TS*BA)
#define GBLK 128           // persistent blocks (co-resident)
#define TILE 5120          // 128 rows * 40 padded bf16

// ----------------- device-global scratch -----------------
static __device__ __align__(16) __nv_bfloat16 g_Ahi[(size_t)TBM*DI];
static __device__ __align__(16) __nv_bfloat16 g_Alo[(size_t)TBM*DI];
static __device__ __align__(16) __nv_bfloat16 g_WxThi[(size_t)NG*DI];   // [c][d], K-major
static __device__ __align__(16) __nv_bfloat16 g_WxTlo[(size_t)NG*DI];
static __device__ __align__(16) __nv_bfloat16 g_WhThi[(size_t)NG*HID];  // [c][k], K-major
static __device__ __align__(16) __nv_bfloat16 g_WhTlo[(size_t)NG*HID];
static __device__ __align__(16) float         g_bias[NG];
static __device__ __align__(16) float         g_X[(size_t)TBM*NG];
static __device__ __align__(16) __nv_bfloat16 g_HF[2][BA*HID];          // H hi, A-fragment layout
static __device__ volatile int g_cnt;
static __device__ volatile int g_phase;

// ----------------- helpers -----------------
__device__ __forceinline__ void split_bf16(float v, __nv_bfloat16& hi, __nv_bfloat16& lo) {
    hi = __float2bfloat16(v);
    lo = __float2bfloat16(v - __bfloat162float(hi));
}

__device__ __forceinline__ void mma16816(float* c,
                                         uint32_t a0, uint32_t a1, uint32_t a2, uint32_t a3,
                                         uint32_t b0, uint32_t b1) {
    asm volatile(
        "mma.sync.aligned.m16n8k16.row.col.f32.bf16.bf16.f32 "
        "{%0,%1,%2,%3},{%4,%5,%6,%7},{%8,%9},{%0,%1,%2,%3};\n"
        : "+f"(c[0]), "+f"(c[1]), "+f"(c[2]), "+f"(c[3])
        : "r"(a0), "r"(a1), "r"(a2), "r"(a3), "r"(b0), "r"(b1));
}

__device__ __forceinline__ float sigf(float x) { return 1.f / (1.f + __expf(-x)); }
__device__ __forceinline__ float tanhfast(float x) {
    float ax = fminf(fmaxf(x, -15.f), 15.f);
    float e  = __expf(2.f * ax);
    return (e - 1.f) / (e + 1.f);
}

__device__ __forceinline__ int cglob_f(int cl, int blk) {
    return (cl >> 2) * HID + blk * 4 + (cl & 3);
}

__device__ __forceinline__ void st_cg_b16(__nv_bfloat16* p, __nv_bfloat16 v) {
    unsigned short u = *(unsigned short*)&v;
    asm volatile("st.global.cg.b16 [%0], %1;" :: "l"(p), "h"(u) : "memory");
}

__device__ __forceinline__ void cpa16(__nv_bfloat16* dst, const __nv_bfloat16* src) {
    uint32_t s = (uint32_t)__cvta_generic_to_shared(dst);
    asm volatile("cp.async.cg.shared.global [%0], [%1], 16;\n" :: "r"(s), "l"(src));
}
__device__ __forceinline__ void cpa_commit() { asm volatile("cp.async.commit_group;\n"); }
template<int N> __device__ __forceinline__ void cpa_wait() {
    asm volatile("cp.async.wait_group %0;\n" :: "n"(N));
}

// ----------------- init -----------------
__global__ void k_init() {
    int i = blockIdx.x * blockDim.x + threadIdx.x;
    if (i < 2 * BA * HID) ((__nv_bfloat16*)g_HF)[i] = __float2bfloat16(0.f);
    if (i == 0) { g_cnt = 0; g_phase = 0; }
}

// ----------------- inputs -> split bf16 -----------------
__global__ void k_conv_in(const float* __restrict__ in) {
    size_t i = (size_t)blockIdx.x * blockDim.x + threadIdx.x;
    const size_t n4 = (size_t)TBM * DI / 4;
    if (i >= n4) return;
    float4 v = reinterpret_cast<const float4*>(in)[i];
    __nv_bfloat16 h0,h1,h2,h3,l0,l1,l2,l3;
    split_bf16(v.x, h0, l0); split_bf16(v.y, h1, l1);
    split_bf16(v.z, h2, l2); split_bf16(v.w, h3, l3);
    __nv_bfloat162* ph = reinterpret_cast<__nv_bfloat162*>(g_Ahi + 4*i);
    __nv_bfloat162* pl = reinterpret_cast<__nv_bfloat162*>(g_Alo + 4*i);
    ph[0] = __halves2bfloat162(h0, h1); ph[1] = __halves2bfloat162(h2, h3);
    pl[0] = __halves2bfloat162(l0, l1); pl[1] = __halves2bfloat162(l2, l3);
}

// ----------------- weights -> split bf16, transposed; biases -----------------
__global__ void k_conv_w(const float* __restrict__ Wxi, const float* __restrict__ Wxf,
                         const float* __restrict__ Wxo, const float* __restrict__ Wxc,
                         const float* __restrict__ Whi, const float* __restrict__ Whf,
                         const float* __restrict__ Who, const float* __restrict__ Whc,
                         const float* __restrict__ bi,  const float* __restrict__ bff,
                         const float* __restrict__ bo,  const float* __restrict__ bc) {
    const int NW = NG * DI;
    int stride = gridDim.x * blockDim.x;
    for (int i = blockIdx.x * blockDim.x + threadIdx.x; i < 2*NW + NG; i += stride) {
        if (i < NW) {
            int c = i >> 9, d = i & 511;
            int gg = c >> 9, h = c & 511;
            const float* W = gg == 0 ? Wxi : (gg == 1 ? Wxf : (gg == 2 ? Wxo : Wxc));
            __nv_bfloat16 hi, lo; split_bf16(W[d*HID + h], hi, lo);
            g_WxThi[i] = hi; g_WxTlo[i] = lo;
        } else if (i < 2*NW) {
            int j = i - NW;
            int c = j >> 9, k = j & 511;
            int gg = c >> 9, h = c & 511;
            const float* W = gg == 0 ? Whi : (gg == 1 ? Whf : (gg == 2 ? Who : Whc));
            __nv_bfloat16 hi, lo; split_bf16(W[k*HID + h], hi, lo);
            g_WhThi[j] = hi; g_WhTlo[j] = lo;
        } else {
            int c = i - 2*NW;
            int gg = c >> 9, h = c & 511;
            const float* bb = gg == 0 ? bi : (gg == 1 ? bff : (gg == 2 ? bo : bc));
            g_bias[c] = bb[h];
        }
    }
}

// ----------------- phase 1: g_X = inputs @ Wx + bias (cp.async 2-stage) -----------------
extern __shared__ __nv_bfloat16 smx[];   // 2 stages * 4 arrays * TILE

__device__ __forceinline__ void gx_prefetch(int ck, int s, int row0, int col0, int lr, int lh) {
    size_t gA = (size_t)(row0 + lr) * DI + ck*32 + lh*16;
    size_t gB = (size_t)(col0 + lr) * DI + ck*32 + lh*16;
    int so = lr*40 + lh*16;
    __nv_bfloat16* base = smx + (size_t)s*4*TILE;
    cpa16(base + 0*TILE + so,     g_Ahi  + gA);
    cpa16(base + 0*TILE + so + 8, g_Ahi  + gA + 8);
    cpa16(base + 1*TILE + so,     g_Alo  + gA);
    cpa16(base + 1*TILE + so + 8, g_Alo  + gA + 8);
    cpa16(base + 2*TILE + so,     g_WxThi + gB);
    cpa16(base + 2*TILE + so + 8, g_WxThi + gB + 8);
    cpa16(base + 3*TILE + so,     g_WxTlo + gB);
    cpa16(base + 3*TILE + so + 8, g_WxTlo + gB + 8);
}

__global__ __launch_bounds__(256, 1) void k_gemm_x() {
    const int tid = threadIdx.x, w = tid >> 5, l = tid & 31;
    const int wm = w & 3, wn = w >> 2, r = l >> 2, q = l & 3;
    const int row0 = blockIdx.x * 128, col0 = blockIdx.y * 128;
    const int lr = tid >> 1, lh = tid & 1;

    float acc[2][8][4];
    #pragma unroll
    for (int a = 0; a < 2; a++)
        #pragma unroll
        for (int b = 0; b < 8; b++)
            #pragma unroll
            for (int c = 0; c < 4; c++) acc[a][b][c] = 0.f;

    gx_prefetch(0, 0, row0, col0, lr, lh);
    cpa_commit();

    for (int ck = 0; ck < 16; ck++) {
        if (ck < 15) {
            gx_prefetch(ck + 1, (ck + 1) & 1, row0, col0, lr, lh);
            cpa_commit();
            cpa_wait<1>();
        } else {
            cpa_wait<0>();
        }
        __syncthreads();

        const __nv_bfloat16* base = smx + (size_t)(ck & 1)*4*TILE;
        const __nv_bfloat16* Ah_s = base + 0*TILE;
        const __nv_bfloat16* Al_s = base + 1*TILE;
        const __nv_bfloat16* Bh_s = base + 2*TILE;
        const __nv_bfloat16* Bl_s = base + 3*TILE;

        #pragma unroll
        for (int kt = 0; kt < 2; kt++) {
            const int ca = kt*16 + 2*q;
            uint32_t Ahf[2][4], Alf[2][4];
            #pragma unroll
            for (int mt = 0; mt < 2; mt++) {
                int ra = (wm*32 + mt*16 + r) * 40;
                Ahf[mt][0] = *(const uint32_t*)&Ah_s[ra + ca];
                Ahf[mt][1] = *(const uint32_t*)&Ah_s[ra + 320 + ca];
                Ahf[mt][2] = *(const uint32_t*)&Ah_s[ra + ca + 8];
                Ahf[mt][3] = *(const uint32_t*)&Ah_s[ra + 320 + ca + 8];
                Alf[mt][0] = *(const uint32_t*)&Al_s[ra + ca];
                Alf[mt][1] = *(const uint32_t*)&Al_s[ra + 320 + ca];
                Alf[mt][2] = *(const uint32_t*)&Al_s[ra + ca + 8];
                Alf[mt][3] = *(const uint32_t*)&Al_s[ra + 320 + ca + 8];
            }
            #pragma unroll
            for (int nt = 0; nt < 8; nt++) {
                int rb2 = (wn*64 + nt*8 + r) * 40;
                uint32_t bh0 = *(const uint32_t*)&Bh_s[rb2 + ca];
                uint32_t bh1 = *(const uint32_t*)&Bh_s[rb2 + ca + 8];
                uint32_t bl0 = *(const uint32_t*)&Bl_s[rb2 + ca];
                uint32_t bl1 = *(const uint32_t*)&Bl_s[rb2 + ca + 8];
                #pragma unroll
                for (int mt = 0; mt < 2; mt++) {
                    mma16816(acc[mt][nt], Ahf[mt][0], Ahf[mt][1], Ahf[mt][2], Ahf[mt][3], bh0, bh1);
                    mma16816(acc[mt][nt], Alf[mt][0], Alf[mt][1], Alf[mt][2], Alf[mt][3], bh0, bh1);
                    mma16816(acc[mt][nt], Ahf[mt][0], Ahf[mt][1], Ahf[mt][2], Ahf[mt][3], bl0, bl1);
                }
            }
        }
        __syncthreads();
    }

    #pragma unroll
    for (int mt = 0; mt < 2; mt++) {
        #pragma unroll
        for (int nt = 0; nt < 8; nt++) {
            int grow = row0 + wm*32 + mt*16 + r;
            int gcol = col0 + wn*64 + nt*8 + 2*q;
            float2 bb = *(const float2*)&g_bias[gcol];
            float2 v0 = make_float2(acc[mt][nt][0] + bb.x, acc[mt][nt][1] + bb.y);
            float2 v1 = make_float2(acc[mt][nt][2] + bb.x, acc[mt][nt][3] + bb.y);
            *(float2*)&g_X[(size_t)grow * NG + gcol]       = v0;
            *(float2*)&g_X[(size_t)(grow + 8) * NG + gcol] = v1;
        }
    }
}

// ----------------- grid barrier (sense reversal) -----------------
__device__ __forceinline__ void gridbar(int& ph) {
    __syncthreads();
    if (threadIdx.x == 0) {
        __threadfence();
        if (atomicAdd((int*)&g_cnt, 1) == GBLK - 1) {
            g_cnt = 0;
            __threadfence();
            g_phase = ph ^ 1;
        } else {
            while (g_phase == ph) { }
        }
    }
    __syncthreads();
    ph ^= 1;
}

// ----------------- phase 2: persistent LSTM recurrence -----------------
// H stored bf16-hi only, in exact A-fragment order:
//   offset = ((mrow*32 + ktg)*32 + lane)*8 + reg*2 + byte
__global__ __launch_bounds__(256, 1) void k_lstm(float* __restrict__ out) {
    __shared__ __nv_bfloat16 WFlo[16*520];
    __shared__ float preA[64*20];
    __shared__ float preB[64*20];

    const int tid = threadIdx.x, w = tid >> 5, l = tid & 31;
    const int m = w & 3, kh = w >> 2, r = l >> 2, q = l & 3;
    const int blk = blockIdx.x;

    // Wh-hi fragments in registers (loop-invariant; each warp owns half of K)
    uint32_t Bh[2][16][2];
    #pragma unroll
    for (int nt = 0; nt < 2; nt++) {
        int cg = cglob_f(nt*8 + r, blk);
        const __nv_bfloat16* wp = g_WhThi + (size_t)cg * HID;
        #pragma unroll
        for (int ktl = 0; ktl < 16; ktl++) {
            int kg16 = (kh*16 + ktl) * 16;
            Bh[nt][ktl][0] = *(const uint32_t*)(wp + kg16 + 2*q);
            Bh[nt][ktl][1] = *(const uint32_t*)(wp + kg16 + 2*q + 8);
        }
    }
    // Wh-lo fragments in smem
    for (int i = tid; i < 4096; i += 256) {
        int j = i & 1, qq = (i >> 1) & 3, kt = (i >> 3) & 31, n = (i >> 8) & 15;
        int cg = cglob_f(n, blk);
        uint32_t v = *(const uint32_t*)(g_WhTlo + (size_t)cg * HID + kt*16 + 2*qq + 8*j);
        *(uint32_t*)&WFlo[n*520 + (kt*4 + qq)*4 + j*2] = v;
    }
    __syncthreads();

    float C = 0.f;
    int phase = 0;
    const int eb = tid >> 2, ehl = tid & 3;
    const int hg = blk*4 + ehl;
    // producer store offset for H(eb, hg) in fragment layout
    const int mrow = eb >> 4, rloc = eb & 15, pktg = hg >> 4, kk = hg & 15;
    const int plane = ((rloc & 7) << 2) | ((kk & 7) >> 1);
    const int preg  = ((rloc >> 3) & 1) | ((kk >> 3) << 1);
    const int widx  = ((mrow*32 + pktg)*32 + plane)*8 + preg*2 + (kk & 1);

    for (int t = 0; t < TS; t++) {
        const int rb = t & 1, wbuf = rb ^ 1;
        float acc[2][4];
        if (kh == 0) {
            #pragma unroll
            for (int nt = 0; nt < 2; nt++) {
                int cg = cglob_f(nt*8 + 2*q, blk);
                size_t row = (size_t)(t*BA + m*16 + r);
                float2 v01 = *(const float2*)&g_X[row * NG + cg];
                float2 v23 = *(const float2*)&g_X[(row + 8) * NG + cg];
                acc[nt][0] = v01.x; acc[nt][1] = v01.y;
                acc[nt][2] = v23.x; acc[nt][3] = v23.y;
            }
        } else {
            #pragma unroll
            for (int nt = 0; nt < 2; nt++)
                #pragma unroll
                for (int c = 0; c < 4; c++) acc[nt][c] = 0.f;
        }

        gridbar(phase);   // H(t-1) now visible

        const __nv_bfloat16* Hh = g_HF[rb];
        #pragma unroll
        for (int ktl = 0; ktl < 16; ktl++) {
            int ktg = kh*16 + ktl;
            uint4 a = __ldcg((const uint4*)(Hh + ((m*32 + ktg)*32 + l)*8));
            #pragma unroll
            for (int nt = 0; nt < 2; nt++) {
                uint2 bl = *(const uint2*)&WFlo[(nt*8 + r)*520 + (ktg*4 + q)*4];
                mma16816(acc[nt], a.x, a.y, a.z, a.w, Bh[nt][ktl][0], Bh[nt][ktl][1]);
                mma16816(acc[nt], a.x, a.y, a.z, a.w, bl.x, bl.y);
            }
        }

        float* pre = (kh == 0) ? preA : preB;
        #pragma unroll
        for (int nt = 0; nt < 2; nt++) {
            int c0 = nt*8 + 2*q;
            pre[(m*16 + r)*20 + c0]         = acc[nt][0];
            pre[(m*16 + r)*20 + c0 + 1]     = acc[nt][1];
            pre[(m*16 + r + 8)*20 + c0]     = acc[nt][2];
            pre[(m*16 + r + 8)*20 + c0 + 1] = acc[nt][3];
        }
        __syncthreads();

        float xi = preA[eb*20 + ehl]      + preB[eb*20 + ehl];
        float xf = preA[eb*20 + 4 + ehl]  + preB[eb*20 + 4 + ehl];
        float xo = preA[eb*20 + 8 + ehl]  + preB[eb*20 + 8 + ehl];
        float xc = preA[eb*20 + 12 + ehl] + preB[eb*20 + 12 + ehl];
        float I  = sigf(xi), F = sigf(xf), O = sigf(xo);
        float Ct = tanhfast(xc);
        C = F*C + I*Ct;
        float Hn = O * tanhfast(C);

        out[((size_t)t*BA + eb)*HID + hg] = Hn;
        if (t == TS - 1) {
            out[(size_t)TS*BA*HID + (size_t)eb*HID + hg]                  = Hn;
            out[(size_t)TS*BA*HID + (size_t)BA*HID + (size_t)eb*HID + hg] = C;
        }
        st_cg_b16(&g_HF[wbuf][widx], __float2bfloat16(Hn));
    }
}

// ----------------- launch -----------------
extern "C" void kernel_launch(void* const* d_in, const int* in_sizes, int n_in,
                              void* d_out, int out_size) {
    const float* inp = (const float*)d_in[0];
    const float* Wxi = (const float*)d_in[1];
    const float* Whi = (const float*)d_in[2];
    const float* bi  = (const float*)d_in[3];
    const float* Wxf = (const float*)d_in[4];
    const float* Whf = (const float*)d_in[5];
    const float* bf  = (const float*)d_in[6];
    const float* Wxo = (const float*)d_in[7];
    const float* Who = (const float*)d_in[8];
    const float* bo  = (const float*)d_in[9];
    const float* Wxc = (const float*)d_in[10];
    const float* Whc = (const float*)d_in[11];
    const float* bc  = (const float*)d_in[12];
    float* out = (float*)d_out;

    static int smem_set = 0;
    if (!smem_set) {
        cudaFuncSetAttribute(k_gemm_x, cudaFuncAttributeMaxDynamicSharedMemorySize,
                             2*4*TILE*(int)sizeof(__nv_bfloat16));
        smem_set = 1;
    }

    k_init<<<256, 256>>>();
    k_conv_in<<<16384, 256>>>(inp);
    k_conv_w<<<2048, 256>>>(Wxi, Wxf, Wxo, Wxc, Whi, Whf, Who, Whc, bi, bf, bo, bc);
    k_gemm_x<<<dim3(256, 16), 256, 2*4*TILE*sizeof(__nv_bfloat16)>>>();
    k_lstm<<<GBLK, 256>>>(out);
}

// round 4
// speedup vs baseline: 1.5576x; 1.0412x over previous
#include <cuda_runtime.h>
#include <cuda_bf16.h>
#include <stdint.h>

#define TS   512
#define BA   64
#define DI   512
#define HID  512
#define NG   2048          // 4 gates * HID; gate order 0=i,1=f,2=o,3=c
#define TBM  (TS*BA)
#define GBLK 128           // persistent blocks (co-resident)
#define TILE 5120          // 128 rows * 40 padded bf16

// ----------------- device-global scratch -----------------
static __device__ __align__(16) __nv_bfloat16 g_Ahi[(size_t)TBM*DI];
static __device__ __align__(16) __nv_bfloat16 g_Alo[(size_t)TBM*DI];
static __device__ __align__(16) __nv_bfloat16 g_WxThi[(size_t)NG*DI];   // [c][d], K-major
static __device__ __align__(16) __nv_bfloat16 g_WxTlo[(size_t)NG*DI];
static __device__ __align__(16) __nv_bfloat16 g_WhThi[(size_t)NG*HID];  // [c][k], K-major
static __device__ __align__(16) __nv_bfloat16 g_WhTlo[(size_t)NG*HID];
static __device__ __align__(16) float         g_bias[NG];
static __device__ __align__(16) float         g_X[(size_t)TBM*NG];
static __device__ __align__(16) __nv_bfloat16 g_HF[2][BA*HID];          // H hi, A-fragment layout
static __device__ int g_cnt2;
static __device__ int g_phase2;

// ----------------- helpers -----------------
__device__ __forceinline__ void split_bf16(float v, __nv_bfloat16& hi, __nv_bfloat16& lo) {
    hi = __float2bfloat16(v);
    lo = __float2bfloat16(v - __bfloat162float(hi));
}

__device__ __forceinline__ void mma16816(float* c,
                                         uint32_t a0, uint32_t a1, uint32_t a2, uint32_t a3,
                                         uint32_t b0, uint32_t b1) {
    asm volatile(
        "mma.sync.aligned.m16n8k16.row.col.f32.bf16.bf16.f32 "
        "{%0,%1,%2,%3},{%4,%5,%6,%7},{%8,%9},{%0,%1,%2,%3};\n"
        : "+f"(c[0]), "+f"(c[1]), "+f"(c[2]), "+f"(c[3])
        : "r"(a0), "r"(a1), "r"(a2), "r"(a3), "r"(b0), "r"(b1));
}

__device__ __forceinline__ float sigf(float x) { return 1.f / (1.f + __expf(-x)); }
__device__ __forceinline__ float tanhfast(float x) {
    float ax = fminf(fmaxf(x, -15.f), 15.f);
    float e  = __expf(2.f * ax);
    return (e - 1.f) / (e + 1.f);
}

__device__ __forceinline__ int cglob_f(int cl, int blk) {
    return (cl >> 2) * HID + blk * 4 + (cl & 3);
}

__device__ __forceinline__ void st_cg_b16(__nv_bfloat16* p, __nv_bfloat16 v) {
    unsigned short u = *(unsigned short*)&v;
    asm volatile("st.global.cg.b16 [%0], %1;" :: "l"(p), "h"(u) : "memory");
}

__device__ __forceinline__ void cpa16(__nv_bfloat16* dst, const __nv_bfloat16* src) {
    uint32_t s = (uint32_t)__cvta_generic_to_shared(dst);
    asm volatile("cp.async.cg.shared.global [%0], [%1], 16;\n" :: "r"(s), "l"(src));
}
__device__ __forceinline__ void cpa_commit() { asm volatile("cp.async.commit_group;\n"); }
template<int N> __device__ __forceinline__ void cpa_wait() {
    asm volatile("cp.async.wait_group %0;\n" :: "n"(N));
}

// ----------------- fence-free grid barrier (release/acquire) -----------------
__device__ __forceinline__ void bar_arrive(int next) {
    __syncthreads();   // all threads' H stores issued before leader's release
    if (threadIdx.x == 0) {
        int old;
        asm volatile("atom.release.gpu.global.add.s32 %0, [%1], %2;"
                     : "=r"(old) : "l"(&g_cnt2), "r"(1) : "memory");
        if (old == GBLK - 1) {
            asm volatile("st.relaxed.gpu.global.s32 [%0], %1;" :: "l"(&g_cnt2), "r"(0) : "memory");
            asm volatile("st.release.gpu.global.s32 [%0], %1;" :: "l"(&g_phase2), "r"(next) : "memory");
        }
    }
}
__device__ __forceinline__ void bar_wait(int target) {
    if (threadIdx.x == 0) {
        int v;
        do {
            asm volatile("ld.acquire.gpu.global.s32 %0, [%1];" : "=r"(v) : "l"(&g_phase2) : "memory");
        } while (v < target);
    }
    __syncthreads();
}

// ----------------- init -----------------
__global__ void k_init() {
    int i = blockIdx.x * blockDim.x + threadIdx.x;
    if (i < 2 * BA * HID) ((__nv_bfloat16*)g_HF)[i] = __float2bfloat16(0.f);
    if (i == 0) { g_cnt2 = 0; g_phase2 = 0; }
}

// ----------------- inputs -> split bf16 -----------------
__global__ void k_conv_in(const float* __restrict__ in) {
    size_t i = (size_t)blockIdx.x * blockDim.x + threadIdx.x;
    const size_t n4 = (size_t)TBM * DI / 4;
    if (i >= n4) return;
    float4 v = reinterpret_cast<const float4*>(in)[i];
    __nv_bfloat16 h0,h1,h2,h3,l0,l1,l2,l3;
    split_bf16(v.x, h0, l0); split_bf16(v.y, h1, l1);
    split_bf16(v.z, h2, l2); split_bf16(v.w, h3, l3);
    __nv_bfloat162* ph = reinterpret_cast<__nv_bfloat162*>(g_Ahi + 4*i);
    __nv_bfloat162* pl = reinterpret_cast<__nv_bfloat162*>(g_Alo + 4*i);
    ph[0] = __halves2bfloat162(h0, h1); ph[1] = __halves2bfloat162(h2, h3);
    pl[0] = __halves2bfloat162(l0, l1); pl[1] = __halves2bfloat162(l2, l3);
}

// ----------------- weights -> split bf16, transposed; biases -----------------
__global__ void k_conv_w(const float* __restrict__ Wxi, const float* __restrict__ Wxf,
                         const float* __restrict__ Wxo, const float* __restrict__ Wxc,
                         const float* __restrict__ Whi, const float* __restrict__ Whf,
                         const float* __restrict__ Who, const float* __restrict__ Whc,
                         const float* __restrict__ bi,  const float* __restrict__ bff,
                         const float* __restrict__ bo,  const float* __restrict__ bc) {
    const int NW = NG * DI;
    int stride = gridDim.x * blockDim.x;
    for (int i = blockIdx.x * blockDim.x + threadIdx.x; i < 2*NW + NG; i += stride) {
        if (i < NW) {
            int c = i >> 9, d = i & 511;
            int gg = c >> 9, h = c & 511;
            const float* W = gg == 0 ? Wxi : (gg == 1 ? Wxf : (gg == 2 ? Wxo : Wxc));
            __nv_bfloat16 hi, lo; split_bf16(W[d*HID + h], hi, lo);
            g_WxThi[i] = hi; g_WxTlo[i] = lo;
        } else if (i < 2*NW) {
            int j = i - NW;
            int c = j >> 9, k = j & 511;
            int gg = c >> 9, h = c & 511;
            const float* W = gg == 0 ? Whi : (gg == 1 ? Whf : (gg == 2 ? Who : Whc));
            __nv_bfloat16 hi, lo; split_bf16(W[k*HID + h], hi, lo);
            g_WhThi[j] = hi; g_WhTlo[j] = lo;
        } else {
            int c = i - 2*NW;
            int gg = c >> 9, h = c & 511;
            const float* bb = gg == 0 ? bi : (gg == 1 ? bff : (gg == 2 ? bo : bc));
            g_bias[c] = bb[h];
        }
    }
}

// ----------------- phase 1: g_X = inputs @ Wx + bias (cp.async 2-stage, 2 CTA/SM) -----------------
extern __shared__ __nv_bfloat16 smx[];   // 2 stages * 4 arrays * TILE

__device__ __forceinline__ void gx_prefetch(int ck, int s, int row0, int col0, int lr, int lh) {
    size_t gA = (size_t)(row0 + lr) * DI + ck*32 + lh*16;
    size_t gB = (size_t)(col0 + lr) * DI + ck*32 + lh*16;
    int so = lr*40 + lh*16;
    __nv_bfloat16* base = smx + (size_t)s*4*TILE;
    cpa16(base + 0*TILE + so,     g_Ahi  + gA);
    cpa16(base + 0*TILE + so + 8, g_Ahi  + gA + 8);
    cpa16(base + 1*TILE + so,     g_Alo  + gA);
    cpa16(base + 1*TILE + so + 8, g_Alo  + gA + 8);
    cpa16(base + 2*TILE + so,     g_WxThi + gB);
    cpa16(base + 2*TILE + so + 8, g_WxThi + gB + 8);
    cpa16(base + 3*TILE + so,     g_WxTlo + gB);
    cpa16(base + 3*TILE + so + 8, g_WxTlo + gB + 8);
}

__global__ __launch_bounds__(256, 2) void k_gemm_x() {
    const int tid = threadIdx.x, w = tid >> 5, l = tid & 31;
    const int wm = w & 3, wn = w >> 2, r = l >> 2, q = l & 3;
    const int row0 = blockIdx.x * 128, col0 = blockIdx.y * 128;
    const int lr = tid >> 1, lh = tid & 1;

    float acc[2][8][4];
    #pragma unroll
    for (int a = 0; a < 2; a++)
        #pragma unroll
        for (int b = 0; b < 8; b++)
            #pragma unroll
            for (int c = 0; c < 4; c++) acc[a][b][c] = 0.f;

    gx_prefetch(0, 0, row0, col0, lr, lh);
    cpa_commit();

    for (int ck = 0; ck < 16; ck++) {
        if (ck < 15) {
            gx_prefetch(ck + 1, (ck + 1) & 1, row0, col0, lr, lh);
            cpa_commit();
            cpa_wait<1>();
        } else {
            cpa_wait<0>();
        }
        __syncthreads();

        const __nv_bfloat16* base = smx + (size_t)(ck & 1)*4*TILE;
        const __nv_bfloat16* Ah_s = base + 0*TILE;
        const __nv_bfloat16* Al_s = base + 1*TILE;
        const __nv_bfloat16* Bh_s = base + 2*TILE;
        const __nv_bfloat16* Bl_s = base + 3*TILE;

        #pragma unroll
        for (int kt = 0; kt < 2; kt++) {
            const int ca = kt*16 + 2*q;
            uint32_t Ahf[2][4], Alf[2][4];
            #pragma unroll
            for (int mt = 0; mt < 2; mt++) {
                int ra = (wm*32 + mt*16 + r) * 40;
                Ahf[mt][0] = *(const uint32_t*)&Ah_s[ra + ca];
                Ahf[mt][1] = *(const uint32_t*)&Ah_s[ra + 320 + ca];
                Ahf[mt][2] = *(const uint32_t*)&Ah_s[ra + ca + 8];
                Ahf[mt][3] = *(const uint32_t*)&Ah_s[ra + 320 + ca + 8];
                Alf[mt][0] = *(const uint32_t*)&Al_s[ra + ca];
                Alf[mt][1] = *(const uint32_t*)&Al_s[ra + 320 + ca];
                Alf[mt][2] = *(const uint32_t*)&Al_s[ra + ca + 8];
                Alf[mt][3] = *(const uint32_t*)&Al_s[ra + 320 + ca + 8];
            }
            #pragma unroll
            for (int nt = 0; nt < 8; nt++) {
                int rb2 = (wn*64 + nt*8 + r) * 40;
                uint32_t bh0 = *(const uint32_t*)&Bh_s[rb2 + ca];
                uint32_t bh1 = *(const uint32_t*)&Bh_s[rb2 + ca + 8];
                uint32_t bl0 = *(const uint32_t*)&Bl_s[rb2 + ca];
                uint32_t bl1 = *(const uint32_t*)&Bl_s[rb2 + ca + 8];
                #pragma unroll
                for (int mt = 0; mt < 2; mt++) {
                    mma16816(acc[mt][nt], Ahf[mt][0], Ahf[mt][1], Ahf[mt][2], Ahf[mt][3], bh0, bh1);
                    mma16816(acc[mt][nt], Alf[mt][0], Alf[mt][1], Alf[mt][2], Alf[mt][3], bh0, bh1);
                    mma16816(acc[mt][nt], Ahf[mt][0], Ahf[mt][1], Ahf[mt][2], Ahf[mt][3], bl0, bl1);
                }
            }
        }
        __syncthreads();
    }

    #pragma unroll
    for (int mt = 0; mt < 2; mt++) {
        #pragma unroll
        for (int nt = 0; nt < 8; nt++) {
            int grow = row0 + wm*32 + mt*16 + r;
            int gcol = col0 + wn*64 + nt*8 + 2*q;
            float2 bb = *(const float2*)&g_bias[gcol];
            float2 v0 = make_float2(acc[mt][nt][0] + bb.x, acc[mt][nt][1] + bb.y);
            float2 v1 = make_float2(acc[mt][nt][2] + bb.x, acc[mt][nt][3] + bb.y);
            *(float2*)&g_X[(size_t)grow * NG + gcol]       = v0;
            *(float2*)&g_X[(size_t)(grow + 8) * NG + gcol] = v1;
        }
    }
}

// ----------------- phase 2: persistent LSTM recurrence -----------------
// H stored bf16-hi only, in exact A-fragment order:
//   offset = ((mrow*32 + ktg)*32 + lane)*8 + reg*2 + byte
__global__ __launch_bounds__(256, 1) void k_lstm(float* __restrict__ out) {
    __shared__ __nv_bfloat16 WFlo[16*520];
    __shared__ float preA[64*20];
    __shared__ float preB[64*20];

    const int tid = threadIdx.x, w = tid >> 5, l = tid & 31;
    const int m = w & 3, kh = w >> 2, r = l >> 2, q = l & 3;
    const int blk = blockIdx.x;

    // Wh-hi fragments in registers (loop-invariant; each warp owns half of K)
    uint32_t Bh[2][16][2];
    #pragma unroll
    for (int nt = 0; nt < 2; nt++) {
        int cg = cglob_f(nt*8 + r, blk);
        const __nv_bfloat16* wp = g_WhThi + (size_t)cg * HID;
        #pragma unroll
        for (int ktl = 0; ktl < 16; ktl++) {
            int kg16 = (kh*16 + ktl) * 16;
            Bh[nt][ktl][0] = *(const uint32_t*)(wp + kg16 + 2*q);
            Bh[nt][ktl][1] = *(const uint32_t*)(wp + kg16 + 2*q + 8);
        }
    }
    // Wh-lo fragments in smem
    for (int i = tid; i < 4096; i += 256) {
        int j = i & 1, qq = (i >> 1) & 3, kt = (i >> 3) & 31, n = (i >> 8) & 15;
        int cg = cglob_f(n, blk);
        uint32_t v = *(const uint32_t*)(g_WhTlo + (size_t)cg * HID + kt*16 + 2*qq + 8*j);
        *(uint32_t*)&WFlo[n*520 + (kt*4 + qq)*4 + j*2] = v;
    }
    __syncthreads();

    float C = 0.f;
    const int eb = tid >> 2, ehl = tid & 3;
    const int hg = blk*4 + ehl;
    const int mrow = eb >> 4, rloc = eb & 15, pktg = hg >> 4, kk = hg & 15;
    const int plane = ((rloc & 7) << 2) | ((kk & 7) >> 1);
    const int preg  = ((rloc >> 3) & 1) | ((kk >> 3) << 1);
    const int widx  = ((mrow*32 + pktg)*32 + plane)*8 + preg*2 + (kk & 1);

    for (int t = 0; t < TS; t++) {
        const int rb = t & 1;
        // acc init from g_X (off inter-block critical path: runs before wait)
        float acc[2][4], acc2[2][4];
        if (kh == 0) {
            #pragma unroll
            for (int nt = 0; nt < 2; nt++) {
                int cg = cglob_f(nt*8 + 2*q, blk);
                size_t row = (size_t)(t*BA + m*16 + r);
                float2 v01 = *(const float2*)&g_X[row * NG + cg];
                float2 v23 = *(const float2*)&g_X[(row + 8) * NG + cg];
                acc[nt][0] = v01.x; acc[nt][1] = v01.y;
                acc[nt][2] = v23.x; acc[nt][3] = v23.y;
            }
        } else {
            #pragma unroll
            for (int nt = 0; nt < 2; nt++)
                #pragma unroll
                for (int c = 0; c < 4; c++) acc[nt][c] = 0.f;
        }
        #pragma unroll
        for (int nt = 0; nt < 2; nt++)
            #pragma unroll
            for (int c = 0; c < 4; c++) acc2[nt][c] = 0.f;

        if (t > 0) bar_wait(t);   // H(t-1) visible

        const __nv_bfloat16* Hh = g_HF[rb];
        #pragma unroll
        for (int ktl = 0; ktl < 16; ktl += 2) {
            int ktg0 = kh*16 + ktl, ktg1 = ktg0 + 1;
            uint4 a0 = __ldcg((const uint4*)(Hh + ((m*32 + ktg0)*32 + l)*8));
            uint4 a1 = __ldcg((const uint4*)(Hh + ((m*32 + ktg1)*32 + l)*8));
            #pragma unroll
            for (int nt = 0; nt < 2; nt++) {
                uint2 bl0 = *(const uint2*)&WFlo[(nt*8 + r)*520 + (ktg0*4 + q)*4];
                uint2 bl1 = *(const uint2*)&WFlo[(nt*8 + r)*520 + (ktg1*4 + q)*4];
                mma16816(acc[nt],  a0.x, a0.y, a0.z, a0.w, Bh[nt][ktl][0],   Bh[nt][ktl][1]);
                mma16816(acc[nt],  a0.x, a0.y, a0.z, a0.w, bl0.x, bl0.y);
                mma16816(acc2[nt], a1.x, a1.y, a1.z, a1.w, Bh[nt][ktl+1][0], Bh[nt][ktl+1][1]);
                mma16816(acc2[nt], a1.x, a1.y, a1.z, a1.w, bl1.x, bl1.y);
            }
        }

        float* pre = (kh == 0) ? preA : preB;
        #pragma unroll
        for (int nt = 0; nt < 2; nt++) {
            int c0 = nt*8 + 2*q;
            pre[(m*16 + r)*20 + c0]         = acc[nt][0] + acc2[nt][0];
            pre[(m*16 + r)*20 + c0 + 1]     = acc[nt][1] + acc2[nt][1];
            pre[(m*16 + r + 8)*20 + c0]     = acc[nt][2] + acc2[nt][2];
            pre[(m*16 + r + 8)*20 + c0 + 1] = acc[nt][3] + acc2[nt][3];
        }
        __syncthreads();

        float xi = preA[eb*20 + ehl]      + preB[eb*20 + ehl];
        float xf = preA[eb*20 + 4 + ehl]  + preB[eb*20 + 4 + ehl];
        float xo = preA[eb*20 + 8 + ehl]  + preB[eb*20 + 8 + ehl];
        float xc = preA[eb*20 + 12 + ehl] + preB[eb*20 + 12 + ehl];
        float I  = sigf(xi), F = sigf(xf), O = sigf(xo);
        float Ct = tanhfast(xc);
        C = F*C + I*Ct;
        float Hn = O * tanhfast(C);

        st_cg_b16(&g_HF[rb ^ 1][widx], __float2bfloat16(Hn));
        bar_arrive(t + 1);           // release H(t); includes __syncthreads

        // off the critical path: fp32 outputs
        out[((size_t)t*BA + eb)*HID + hg] = Hn;
        if (t == TS - 1) {
            out[(size_t)TS*BA*HID + (size_t)eb*HID + hg]                  = Hn;
            out[(size_t)TS*BA*HID + (size_t)BA*HID + (size_t)eb*HID + hg] = C;
        }
    }
}

// ----------------- launch -----------------
extern "C" void kernel_launch(void* const* d_in, const int* in_sizes, int n_in,
                              void* d_out, int out_size) {
    const float* inp = (const float*)d_in[0];
    const float* Wxi = (const float*)d_in[1];
    const float* Whi = (const float*)d_in[2];
    const float* bi  = (const float*)d_in[3];
    const float* Wxf = (const float*)d_in[4];
    const float* Whf = (const float*)d_in[5];
    const float* bf  = (const float*)d_in[6];
    const float* Wxo = (const float*)d_in[7];
    const float* Who = (const float*)d_in[8];
    const float* bo  = (const float*)d_in[9];
    const float* Wxc = (const float*)d_in[10];
    const float* Whc = (const float*)d_in[11];
    const float* bc  = (const float*)d_in[12];
    float* out = (float*)d_out;

    static int smem_set = 0;
    if (!smem_set) {
        cudaFuncSetAttribute(k_gemm_x, cudaFuncAttributeMaxDynamicSharedMemorySize,
                             2*4*TILE*(int)sizeof(__nv_bfloat16));
        smem_set = 1;
    }

    k_init<<<256, 256>>>();
    k_conv_in<<<16384, 256>>>(inp);
    k_conv_w<<<2048, 256>>>(Wxi, Wxf, Wxo, Wxc, Whi, Whf, Who, Whc, bi, bf, bo, bc);
    k_gemm_x<<<dim3(256, 16), 256, 2*4*TILE*sizeof(__nv_bfloat16)>>>();
    k_lstm<<<GBLK, 256>>>(out);
}